// round 1
// baseline (speedup 1.0000x reference)
#include <cuda_runtime.h>

#define D_MODEL 1024
#define N_HEAD 16
#define HEAD_DIM 64
#define B_SZ 4
#define TQ 2048
#define TK 8192
#define STRIDE 16
#define L_CTX 512

// Scratch (static device globals; no runtime allocation allowed)
__device__ float g_Qh[(size_t)B_SZ * N_HEAD * TQ * HEAD_DIM];      // [b][h][tq][d]
__device__ float g_Kh[(size_t)B_SZ * N_HEAD * L_CTX * HEAD_DIM];   // [b][h][l][d]
__device__ float g_Vh[(size_t)B_SZ * N_HEAD * L_CTX * HEAD_DIM];   // [b][h][l][d]
__device__ float g_ctx[(size_t)B_SZ * TQ * D_MODEL];               // [b][tq][h*64+d]

// ---------------------------------------------------------------------------
// Q projection: C[8192,1024] = q @ w_q^T + b_q, stored as Qh[b][h][tq][d]
// 64x64 tile, BK=16, 256 threads, 4x4 micro-tile per thread.
// ---------------------------------------------------------------------------
__global__ void proj_q_kernel(const float* __restrict__ A,
                              const float* __restrict__ W,
                              const float* __restrict__ bias) {
    __shared__ float As[16][64];
    __shared__ float Ws[16][64];
    const int m0 = blockIdx.y * 64;
    const int n0 = blockIdx.x * 64;   // 64-col tile == exactly one head
    const int tid = threadIdx.x;
    const int tx = tid & 15, ty = tid >> 4;
    const int lr = tid >> 2;          // 0..63
    const int lc = (tid & 3) * 4;     // 0,4,8,12

    float acc[4][4] = {};

    for (int k0 = 0; k0 < D_MODEL; k0 += 16) {
        float4 av = *(const float4*)(A + (size_t)(m0 + lr) * D_MODEL + k0 + lc);
        float4 wv = *(const float4*)(W + (size_t)(n0 + lr) * D_MODEL + k0 + lc);
        __syncthreads();
        As[lc + 0][lr] = av.x; As[lc + 1][lr] = av.y;
        As[lc + 2][lr] = av.z; As[lc + 3][lr] = av.w;
        Ws[lc + 0][lr] = wv.x; Ws[lc + 1][lr] = wv.y;
        Ws[lc + 2][lr] = wv.z; Ws[lc + 3][lr] = wv.w;
        __syncthreads();
#pragma unroll
        for (int k = 0; k < 16; k++) {
            float4 a = *(const float4*)&As[k][ty * 4];
            float4 w = *(const float4*)&Ws[k][tx * 4];
            acc[0][0] += a.x * w.x; acc[0][1] += a.x * w.y; acc[0][2] += a.x * w.z; acc[0][3] += a.x * w.w;
            acc[1][0] += a.y * w.x; acc[1][1] += a.y * w.y; acc[1][2] += a.y * w.z; acc[1][3] += a.y * w.w;
            acc[2][0] += a.z * w.x; acc[2][1] += a.z * w.y; acc[2][2] += a.z * w.z; acc[2][3] += a.z * w.w;
            acc[3][0] += a.w * w.x; acc[3][1] += a.w * w.y; acc[3][2] += a.w * w.z; acc[3][3] += a.w * w.w;
        }
    }

    const int h = n0 >> 6;
#pragma unroll
    for (int i = 0; i < 4; i++) {
        int m = m0 + ty * 4 + i;
        int b = m >> 11;         // / TQ
        int tq = m & 2047;       // % TQ
        size_t base = (((size_t)b * N_HEAD + h) * TQ + tq) * HEAD_DIM;
#pragma unroll
        for (int j = 0; j < 4; j++) {
            int n = n0 + tx * 4 + j;
            g_Qh[base + (n & 63)] = acc[i][j] + bias[n];
        }
    }
}

// ---------------------------------------------------------------------------
// Sliced K/V projection: for each (b,h):
//   out[b][h][l][:] = X[b, h + 16*l, :] @ W[h*64:(h+1)*64, :]^T + bias[h*64:...]
// M=512 (8 blocks of 64), N=64 (single tile), K=1024.
// ---------------------------------------------------------------------------
__global__ void proj_kv_kernel(const float* __restrict__ X,
                               const float* __restrict__ W,
                               const float* __restrict__ bias,
                               int which) {   // 0 = K, 1 = V
    __shared__ float As[16][64];
    __shared__ float Ws[16][64];
    const int bh = blockIdx.y;
    const int b = bh >> 4, h = bh & 15;
    const int l0 = blockIdx.x * 64;
    const int tid = threadIdx.x;
    const int tx = tid & 15, ty = tid >> 4;
    const int lr = tid >> 2;
    const int lc = (tid & 3) * 4;

    float acc[4][4] = {};
    const float* Xb = X + (size_t)b * TK * D_MODEL;
    const int xrow = h + STRIDE * (l0 + lr);

    for (int k0 = 0; k0 < D_MODEL; k0 += 16) {
        float4 av = *(const float4*)(Xb + (size_t)xrow * D_MODEL + k0 + lc);
        float4 wv = *(const float4*)(W + (size_t)(h * 64 + lr) * D_MODEL + k0 + lc);
        __syncthreads();
        As[lc + 0][lr] = av.x; As[lc + 1][lr] = av.y;
        As[lc + 2][lr] = av.z; As[lc + 3][lr] = av.w;
        Ws[lc + 0][lr] = wv.x; Ws[lc + 1][lr] = wv.y;
        Ws[lc + 2][lr] = wv.z; Ws[lc + 3][lr] = wv.w;
        __syncthreads();
#pragma unroll
        for (int k = 0; k < 16; k++) {
            float4 a = *(const float4*)&As[k][ty * 4];
            float4 w = *(const float4*)&Ws[k][tx * 4];
            acc[0][0] += a.x * w.x; acc[0][1] += a.x * w.y; acc[0][2] += a.x * w.z; acc[0][3] += a.x * w.w;
            acc[1][0] += a.y * w.x; acc[1][1] += a.y * w.y; acc[1][2] += a.y * w.z; acc[1][3] += a.y * w.w;
            acc[2][0] += a.z * w.x; acc[2][1] += a.z * w.y; acc[2][2] += a.z * w.z; acc[2][3] += a.z * w.w;
            acc[3][0] += a.w * w.x; acc[3][1] += a.w * w.y; acc[3][2] += a.w * w.z; acc[3][3] += a.w * w.w;
        }
    }

    float* out = which ? g_Vh : g_Kh;
#pragma unroll
    for (int i = 0; i < 4; i++) {
        size_t base = ((size_t)bh * L_CTX + l0 + ty * 4 + i) * HEAD_DIM + tx * 4;
#pragma unroll
        for (int j = 0; j < 4; j++)
            out[base + j] = acc[i][j] + bias[h * 64 + tx * 4 + j];
    }
}

// ---------------------------------------------------------------------------
// Attention: per (b,h), tile of 32 queries per block.
//   S[32,512] = Q @ Kh^T / 8 (+mask), softmax rows, ctx = S @ Vh -> g_ctx
// Dynamic smem: S (padded stride 516) + Q tile + K/V tile (padded) + mask.
// ---------------------------------------------------------------------------
#define SQ_STRIDE 516
#define KV_STRIDE 68
#define ATTN_SMEM_FLOATS (32 * SQ_STRIDE + 32 * 64 + 64 * KV_STRIDE)
#define ATTN_SMEM_BYTES  (ATTN_SMEM_FLOATS * 4 + L_CTX * 4)

__global__ void attn_kernel(const int* __restrict__ mask) {
    extern __shared__ float sm[];
    float* Sq  = sm;                         // [32][516]
    float* Qs  = Sq + 32 * SQ_STRIDE;        // [32][64]
    float* KVs = Qs + 32 * 64;               // [64][68]
    int*   msk = (int*)(KVs + 64 * KV_STRIDE);  // [512]

    const int bh = blockIdx.y;
    const int b = bh >> 4, h = bh & 15;
    const int q0 = blockIdx.x * 32;
    const int tid = threadIdx.x;
    const int tx = tid & 15, ty = tid >> 4;

    // Load Q tile [32][64]
    const float* Qbase = g_Qh + ((size_t)bh * TQ + q0) * HEAD_DIM;
    for (int i = tid; i < 32 * 16; i += 256) {
        int r = i >> 4, c4 = (i & 15) * 4;
        *(float4*)(Qs + r * 64 + c4) = *(const float4*)(Qbase + r * 64 + c4);
    }
    // Load gathered mask for this head
    for (int i = tid; i < L_CTX; i += 256)
        msk[i] = mask[(size_t)b * TK + h + STRIDE * i];

    // ---- Phase 1: scores ----
    const float* Kbase = g_Kh + (size_t)bh * L_CTX * HEAD_DIM;
    for (int lt = 0; lt < 8; lt++) {
        __syncthreads();
        // load K tile transposed: KVs[d][l]
        for (int i = tid; i < 64 * 16; i += 256) {
            int l = i >> 4, d4 = (i & 15) * 4;
            float4 v = *(const float4*)(Kbase + (size_t)(lt * 64 + l) * HEAD_DIM + d4);
            KVs[(d4 + 0) * KV_STRIDE + l] = v.x;
            KVs[(d4 + 1) * KV_STRIDE + l] = v.y;
            KVs[(d4 + 2) * KV_STRIDE + l] = v.z;
            KVs[(d4 + 3) * KV_STRIDE + l] = v.w;
        }
        __syncthreads();

        float acc[2][4] = {};
#pragma unroll
        for (int k = 0; k < 64; k += 4) {
            float4 a0 = *(const float4*)(Qs + (ty * 2 + 0) * 64 + k);
            float4 a1 = *(const float4*)(Qs + (ty * 2 + 1) * 64 + k);
            float a0f[4] = {a0.x, a0.y, a0.z, a0.w};
            float a1f[4] = {a1.x, a1.y, a1.z, a1.w};
#pragma unroll
            for (int kk = 0; kk < 4; kk++) {
                float4 w = *(const float4*)(KVs + (k + kk) * KV_STRIDE + tx * 4);
                acc[0][0] += a0f[kk] * w.x; acc[0][1] += a0f[kk] * w.y;
                acc[0][2] += a0f[kk] * w.z; acc[0][3] += a0f[kk] * w.w;
                acc[1][0] += a1f[kk] * w.x; acc[1][1] += a1f[kk] * w.y;
                acc[1][2] += a1f[kk] * w.z; acc[1][3] += a1f[kk] * w.w;
            }
        }
#pragma unroll
        for (int i = 0; i < 2; i++) {
#pragma unroll
            for (int j = 0; j < 4; j++) {
                int l = lt * 64 + tx * 4 + j;
                float s = acc[i][j] * 0.125f;
                if (msk[l] == 0) s = -1e9f;
                Sq[(ty * 2 + i) * SQ_STRIDE + l] = s;
            }
        }
    }
    __syncthreads();

    // ---- Phase 2: softmax over each row of S ----
    {
        int row = tid >> 3;
        int lane = tid & 7;
        float* Srow = Sq + row * SQ_STRIDE;
        float m = -1e30f;
        for (int l = lane; l < L_CTX; l += 8) m = fmaxf(m, Srow[l]);
#pragma unroll
        for (int o = 4; o; o >>= 1) m = fmaxf(m, __shfl_xor_sync(0xffffffffu, m, o));
        float ssum = 0.f;
        for (int l = lane; l < L_CTX; l += 8) {
            float e = __expf(Srow[l] - m);
            Srow[l] = e;
            ssum += e;
        }
#pragma unroll
        for (int o = 4; o; o >>= 1) ssum += __shfl_xor_sync(0xffffffffu, ssum, o);
        float inv = 1.0f / ssum;
        for (int l = lane; l < L_CTX; l += 8) Srow[l] *= inv;
    }

    // ---- Phase 3: ctx = P @ Vh ----
    const float* Vbase = g_Vh + (size_t)bh * L_CTX * HEAD_DIM;
    float cacc[2][4] = {};
    for (int lt = 0; lt < 8; lt++) {
        __syncthreads();
        for (int i = tid; i < 64 * 16; i += 256) {
            int l = i >> 4, d4 = (i & 15) * 4;
            *(float4*)(KVs + l * KV_STRIDE + d4) =
                *(const float4*)(Vbase + (size_t)(lt * 64 + l) * HEAD_DIM + d4);
        }
        __syncthreads();
#pragma unroll
        for (int l = 0; l < 64; l += 4) {
            float4 p0 = *(const float4*)(Sq + (ty * 2 + 0) * SQ_STRIDE + lt * 64 + l);
            float4 p1 = *(const float4*)(Sq + (ty * 2 + 1) * SQ_STRIDE + lt * 64 + l);
            float p0f[4] = {p0.x, p0.y, p0.z, p0.w};
            float p1f[4] = {p1.x, p1.y, p1.z, p1.w};
#pragma unroll
            for (int kk = 0; kk < 4; kk++) {
                float4 v = *(const float4*)(KVs + (l + kk) * KV_STRIDE + tx * 4);
                cacc[0][0] += p0f[kk] * v.x; cacc[0][1] += p0f[kk] * v.y;
                cacc[0][2] += p0f[kk] * v.z; cacc[0][3] += p0f[kk] * v.w;
                cacc[1][0] += p1f[kk] * v.x; cacc[1][1] += p1f[kk] * v.y;
                cacc[1][2] += p1f[kk] * v.z; cacc[1][3] += p1f[kk] * v.w;
            }
        }
    }

    // store ctx[b][tq][h*64 + d]  (contiguous [8192,1024] for O projection)
#pragma unroll
    for (int i = 0; i < 2; i++) {
        size_t base = ((size_t)b * TQ + q0 + ty * 2 + i) * D_MODEL + h * 64 + tx * 4;
        float4 r = make_float4(cacc[i][0], cacc[i][1], cacc[i][2], cacc[i][3]);
        *(float4*)(g_ctx + base) = r;
    }
}

// ---------------------------------------------------------------------------
// O projection: out[8192,1024] = ctx @ w_o^T + b_o
// ---------------------------------------------------------------------------
__global__ void proj_o_kernel(const float* __restrict__ W,
                              const float* __restrict__ bias,
                              float* __restrict__ C) {
    __shared__ float As[16][64];
    __shared__ float Ws[16][64];
    const int m0 = blockIdx.y * 64;
    const int n0 = blockIdx.x * 64;
    const int tid = threadIdx.x;
    const int tx = tid & 15, ty = tid >> 4;
    const int lr = tid >> 2;
    const int lc = (tid & 3) * 4;

    float acc[4][4] = {};

    for (int k0 = 0; k0 < D_MODEL; k0 += 16) {
        float4 av = *(const float4*)(g_ctx + (size_t)(m0 + lr) * D_MODEL + k0 + lc);
        float4 wv = *(const float4*)(W + (size_t)(n0 + lr) * D_MODEL + k0 + lc);
        __syncthreads();
        As[lc + 0][lr] = av.x; As[lc + 1][lr] = av.y;
        As[lc + 2][lr] = av.z; As[lc + 3][lr] = av.w;
        Ws[lc + 0][lr] = wv.x; Ws[lc + 1][lr] = wv.y;
        Ws[lc + 2][lr] = wv.z; Ws[lc + 3][lr] = wv.w;
        __syncthreads();
#pragma unroll
        for (int k = 0; k < 16; k++) {
            float4 a = *(const float4*)&As[k][ty * 4];
            float4 w = *(const float4*)&Ws[k][tx * 4];
            acc[0][0] += a.x * w.x; acc[0][1] += a.x * w.y; acc[0][2] += a.x * w.z; acc[0][3] += a.x * w.w;
            acc[1][0] += a.y * w.x; acc[1][1] += a.y * w.y; acc[1][2] += a.y * w.z; acc[1][3] += a.y * w.w;
            acc[2][0] += a.z * w.x; acc[2][1] += a.z * w.y; acc[2][2] += a.z * w.z; acc[2][3] += a.z * w.w;
            acc[3][0] += a.w * w.x; acc[3][1] += a.w * w.y; acc[3][2] += a.w * w.z; acc[3][3] += a.w * w.w;
        }
    }

#pragma unroll
    for (int i = 0; i < 4; i++) {
        size_t base = (size_t)(m0 + ty * 4 + i) * D_MODEL + n0 + tx * 4;
#pragma unroll
        for (int j = 0; j < 4; j++)
            C[base + j] = acc[i][j] + bias[n0 + tx * 4 + j];
    }
}

// ---------------------------------------------------------------------------
extern "C" void kernel_launch(void* const* d_in, const int* in_sizes, int n_in,
                              void* d_out, int out_size) {
    const float* q        = (const float*)d_in[0];
    const float* k        = (const float*)d_in[1];
    const float* v        = (const float*)d_in[2];
    const int*   src_mask = (const int*)d_in[3];
    const float* w_q      = (const float*)d_in[4];
    const float* b_q      = (const float*)d_in[5];
    const float* w_k      = (const float*)d_in[6];
    const float* b_k      = (const float*)d_in[7];
    const float* w_v      = (const float*)d_in[8];
    const float* b_v      = (const float*)d_in[9];
    const float* w_o      = (const float*)d_in[10];
    const float* b_o      = (const float*)d_in[11];
    float* out = (float*)d_out;

    cudaFuncSetAttribute(attn_kernel,
                         cudaFuncAttributeMaxDynamicSharedMemorySize,
                         ATTN_SMEM_BYTES);

    proj_q_kernel<<<dim3(D_MODEL / 64, (B_SZ * TQ) / 64), 256>>>(q, w_q, b_q);
    proj_kv_kernel<<<dim3(L_CTX / 64, B_SZ * N_HEAD), 256>>>(k, w_k, b_k, 0);
    proj_kv_kernel<<<dim3(L_CTX / 64, B_SZ * N_HEAD), 256>>>(v, w_v, b_v, 1);
    attn_kernel<<<dim3(TQ / 32, B_SZ * N_HEAD), 256, ATTN_SMEM_BYTES>>>(src_mask);
    proj_o_kernel<<<dim3(D_MODEL / 64, (B_SZ * TQ) / 64), 256>>>(w_o, b_o, out);
}

// round 2
// speedup vs baseline: 1.3396x; 1.3396x over previous
#include <cuda_runtime.h>
#include <cstdint>

#define D_MODEL 1024
#define N_HEAD 16
#define HEAD_DIM 64
#define B_SZ 4
#define TQ 2048
#define TK 8192
#define STRIDE 16
#define L_CTX 512

// Scratch (static device globals; no runtime allocation allowed)
__device__ float g_Qh[(size_t)B_SZ * N_HEAD * TQ * HEAD_DIM];      // [b][h][tq][d]
__device__ float g_Kh[(size_t)B_SZ * N_HEAD * L_CTX * HEAD_DIM];   // [b][h][l][d]
__device__ float g_Vh[(size_t)B_SZ * N_HEAD * L_CTX * HEAD_DIM];   // [b][h][l][d]
__device__ float g_ctx[(size_t)B_SZ * TQ * D_MODEL];               // [b][tq][h*64+d]

// ---------------------------------------------------------------------------
// tf32 helpers
// ---------------------------------------------------------------------------
__device__ __forceinline__ float tf32_round(float x) {
    uint32_t u;
    asm("cvt.rna.tf32.f32 %0, %1;" : "=r"(u) : "f"(x));
    return __uint_as_float(u);
}

__device__ __forceinline__ void mma_tf32(float* c, const uint32_t* a,
                                         uint32_t b0, uint32_t b1) {
    asm volatile(
        "mma.sync.aligned.m16n8k8.row.col.f32.tf32.tf32.f32 "
        "{%0,%1,%2,%3}, {%4,%5,%6,%7}, {%8,%9}, {%0,%1,%2,%3};\n"
        : "+f"(c[0]), "+f"(c[1]), "+f"(c[2]), "+f"(c[3])
        : "r"(a[0]), "r"(a[1]), "r"(a[2]), "r"(a[3]), "r"(b0), "r"(b1));
}

// ---------------------------------------------------------------------------
// tf32 GEMM: C[M,N] = A @ W^T + bias, with mode-specific row gather / output
// MODE 0: Q proj  (A = q [8192,1024], out -> g_Qh[b][h][tq][d])
// MODE 1: K proj  (gathered rows, out -> g_Kh)
// MODE 2: V proj  (gathered rows, out -> g_Vh)
// MODE 3: O proj  (A = g_ctx, out -> C [8192,1024])
// Block: BM=128 x BN, BK=32, 256 threads (8 warps, 4(M) x 2(N)).
// Warp tile: 32 x BN/2; mma m16n8k8, 2 m-frags x (BN/16) n-frags.
// ---------------------------------------------------------------------------
template <int BN, int MODE>
__global__ void __launch_bounds__(256, 2)
tf32_gemm_kernel(const float* __restrict__ Ain,
                 const float* __restrict__ W,
                 const float* __restrict__ bias,
                 float* __restrict__ Cout) {
    __shared__ float As[32][128 + 4];
    __shared__ float Ws[32][BN + 4];

    const int tid = threadIdx.x;
    const int lane = tid & 31, warp = tid >> 5;
    const int gid = lane >> 2, tig = lane & 3;

    // tile origins
    int m0, bh = 0, b = 0, h = 0, n_base = 0;
    const float* A;
    if (MODE == 1 || MODE == 2) {
        bh = blockIdx.y; b = bh >> 4; h = bh & 15;
        m0 = blockIdx.x * 128;                    // l-tile origin
        A = Ain + (size_t)b * TK * D_MODEL;
        n_base = h * 64;                          // weight row offset
    } else {
        m0 = blockIdx.y * 128;
        n_base = blockIdx.x * BN;
        A = (MODE == 3) ? g_ctx : Ain;
    }

    const int wm = (warp >> 1) * 32;              // warp M offset within block
    const int wn = (warp & 1) * (BN / 2);         // warp N offset within block
    constexpr int NF = BN / 16;                   // n-frags per warp

    float acc[2][NF][4];
#pragma unroll
    for (int i = 0; i < 2; i++)
#pragma unroll
        for (int j = 0; j < NF; j++)
#pragma unroll
            for (int r = 0; r < 4; r++) acc[i][j][r] = 0.f;

    for (int k0 = 0; k0 < D_MODEL; k0 += 32) {
        __syncthreads();
        // --- load A tile [128 rows][32 k] into As[k][m] (tf32-rounded) ---
#pragma unroll
        for (int i = 0; i < 4; i++) {
            int idx = tid + i * 256;              // 0..1023
            int row = idx & 127;
            int kc = (idx >> 7) * 4;              // 0,4,...,28
            int grow;
            if (MODE == 1 || MODE == 2) grow = h + STRIDE * (m0 + row);
            else                        grow = m0 + row;
            float4 av = *(const float4*)(A + (size_t)grow * D_MODEL + k0 + kc);
            As[kc + 0][row] = tf32_round(av.x);
            As[kc + 1][row] = tf32_round(av.y);
            As[kc + 2][row] = tf32_round(av.z);
            As[kc + 3][row] = tf32_round(av.w);
        }
        // --- load W tile [BN rows][32 k] into Ws[k][n] (tf32-rounded) ---
#pragma unroll
        for (int i = 0; i < BN / 32; i++) {
            int idx = tid + i * 256;
            int nrow = idx & (BN - 1);
            int kc = (idx / BN) * 4;
            float4 wv = *(const float4*)(W + (size_t)(n_base + nrow) * D_MODEL + k0 + kc);
            Ws[kc + 0][nrow] = tf32_round(wv.x);
            Ws[kc + 1][nrow] = tf32_round(wv.y);
            Ws[kc + 2][nrow] = tf32_round(wv.z);
            Ws[kc + 3][nrow] = tf32_round(wv.w);
        }
        __syncthreads();

        // --- mma over 4 k-steps of 8 ---
#pragma unroll
        for (int ks = 0; ks < 32; ks += 8) {
            uint32_t a[2][4];
#pragma unroll
            for (int mi = 0; mi < 2; mi++) {
                int m = wm + mi * 16 + gid;
                a[mi][0] = __float_as_uint(As[ks + tig][m]);
                a[mi][1] = __float_as_uint(As[ks + tig][m + 8]);
                a[mi][2] = __float_as_uint(As[ks + tig + 4][m]);
                a[mi][3] = __float_as_uint(As[ks + tig + 4][m + 8]);
            }
#pragma unroll
            for (int ni = 0; ni < NF; ni++) {
                int n = wn + ni * 8 + gid;
                uint32_t b0 = __float_as_uint(Ws[ks + tig][n]);
                uint32_t b1 = __float_as_uint(Ws[ks + tig + 4][n]);
                mma_tf32(acc[0][ni], a[0], b0, b1);
                mma_tf32(acc[1][ni], a[1], b0, b1);
            }
        }
    }

    // --- writeback ---
#pragma unroll
    for (int mi = 0; mi < 2; mi++) {
#pragma unroll
        for (int ni = 0; ni < NF; ni++) {
#pragma unroll
            for (int r = 0; r < 4; r++) {
                int ml = wm + mi * 16 + gid + ((r >> 1) ? 8 : 0);
                int nl = wn + ni * 8 + 2 * tig + (r & 1);
                float v = acc[mi][ni][r];
                if (MODE == 0) {
                    int m = m0 + ml;
                    int n = n_base + nl;
                    int bb = m >> 11, tq = m & 2047;
                    int hh = n >> 6, d = n & 63;
                    g_Qh[(((size_t)bb * N_HEAD + hh) * TQ + tq) * HEAD_DIM + d] =
                        v + bias[n];
                } else if (MODE == 1) {
                    g_Kh[((size_t)bh * L_CTX + m0 + ml) * HEAD_DIM + nl] =
                        v + bias[n_base + nl];
                } else if (MODE == 2) {
                    g_Vh[((size_t)bh * L_CTX + m0 + ml) * HEAD_DIM + nl] =
                        v + bias[n_base + nl];
                } else {
                    Cout[(size_t)(m0 + ml) * D_MODEL + n_base + nl] =
                        v + bias[n_base + nl];
                }
            }
        }
    }
}

// ---------------------------------------------------------------------------
// Attention: per (b,h), tile of 32 queries per block. (unchanged from R1)
// ---------------------------------------------------------------------------
#define SQ_STRIDE 516
#define KV_STRIDE 68
#define ATTN_SMEM_FLOATS (32 * SQ_STRIDE + 32 * 64 + 64 * KV_STRIDE)
#define ATTN_SMEM_BYTES  (ATTN_SMEM_FLOATS * 4 + L_CTX * 4)

__global__ void attn_kernel(const int* __restrict__ mask) {
    extern __shared__ float sm[];
    float* Sq  = sm;                         // [32][516]
    float* Qs  = Sq + 32 * SQ_STRIDE;        // [32][64]
    float* KVs = Qs + 32 * 64;               // [64][68]
    int*   msk = (int*)(KVs + 64 * KV_STRIDE);  // [512]

    const int bh = blockIdx.y;
    const int b = bh >> 4, h = bh & 15;
    const int q0 = blockIdx.x * 32;
    const int tid = threadIdx.x;
    const int tx = tid & 15, ty = tid >> 4;

    const float* Qbase = g_Qh + ((size_t)bh * TQ + q0) * HEAD_DIM;
    for (int i = tid; i < 32 * 16; i += 256) {
        int r = i >> 4, c4 = (i & 15) * 4;
        *(float4*)(Qs + r * 64 + c4) = *(const float4*)(Qbase + r * 64 + c4);
    }
    for (int i = tid; i < L_CTX; i += 256)
        msk[i] = mask[(size_t)b * TK + h + STRIDE * i];

    // ---- Phase 1: scores ----
    const float* Kbase = g_Kh + (size_t)bh * L_CTX * HEAD_DIM;
    for (int lt = 0; lt < 8; lt++) {
        __syncthreads();
        for (int i = tid; i < 64 * 16; i += 256) {
            int l = i >> 4, d4 = (i & 15) * 4;
            float4 v = *(const float4*)(Kbase + (size_t)(lt * 64 + l) * HEAD_DIM + d4);
            KVs[(d4 + 0) * KV_STRIDE + l] = v.x;
            KVs[(d4 + 1) * KV_STRIDE + l] = v.y;
            KVs[(d4 + 2) * KV_STRIDE + l] = v.z;
            KVs[(d4 + 3) * KV_STRIDE + l] = v.w;
        }
        __syncthreads();

        float acc[2][4] = {};
#pragma unroll
        for (int k = 0; k < 64; k += 4) {
            float4 a0 = *(const float4*)(Qs + (ty * 2 + 0) * 64 + k);
            float4 a1 = *(const float4*)(Qs + (ty * 2 + 1) * 64 + k);
            float a0f[4] = {a0.x, a0.y, a0.z, a0.w};
            float a1f[4] = {a1.x, a1.y, a1.z, a1.w};
#pragma unroll
            for (int kk = 0; kk < 4; kk++) {
                float4 w = *(const float4*)(KVs + (k + kk) * KV_STRIDE + tx * 4);
                acc[0][0] += a0f[kk] * w.x; acc[0][1] += a0f[kk] * w.y;
                acc[0][2] += a0f[kk] * w.z; acc[0][3] += a0f[kk] * w.w;
                acc[1][0] += a1f[kk] * w.x; acc[1][1] += a1f[kk] * w.y;
                acc[1][2] += a1f[kk] * w.z; acc[1][3] += a1f[kk] * w.w;
            }
        }
#pragma unroll
        for (int i = 0; i < 2; i++) {
#pragma unroll
            for (int j = 0; j < 4; j++) {
                int l = lt * 64 + tx * 4 + j;
                float s = acc[i][j] * 0.125f;
                if (msk[l] == 0) s = -1e9f;
                Sq[(ty * 2 + i) * SQ_STRIDE + l] = s;
            }
        }
    }
    __syncthreads();

    // ---- Phase 2: softmax ----
    {
        int row = tid >> 3;
        int lane = tid & 7;
        float* Srow = Sq + row * SQ_STRIDE;
        float m = -1e30f;
        for (int l = lane; l < L_CTX; l += 8) m = fmaxf(m, Srow[l]);
#pragma unroll
        for (int o = 4; o; o >>= 1) m = fmaxf(m, __shfl_xor_sync(0xffffffffu, m, o));
        float ssum = 0.f;
        for (int l = lane; l < L_CTX; l += 8) {
            float e = __expf(Srow[l] - m);
            Srow[l] = e;
            ssum += e;
        }
#pragma unroll
        for (int o = 4; o; o >>= 1) ssum += __shfl_xor_sync(0xffffffffu, ssum, o);
        float inv = 1.0f / ssum;
        for (int l = lane; l < L_CTX; l += 8) Srow[l] *= inv;
    }

    // ---- Phase 3: ctx = P @ Vh ----
    const float* Vbase = g_Vh + (size_t)bh * L_CTX * HEAD_DIM;
    float cacc[2][4] = {};
    for (int lt = 0; lt < 8; lt++) {
        __syncthreads();
        for (int i = tid; i < 64 * 16; i += 256) {
            int l = i >> 4, d4 = (i & 15) * 4;
            *(float4*)(KVs + l * KV_STRIDE + d4) =
                *(const float4*)(Vbase + (size_t)(lt * 64 + l) * HEAD_DIM + d4);
        }
        __syncthreads();
#pragma unroll
        for (int l = 0; l < 64; l += 4) {
            float4 p0 = *(const float4*)(Sq + (ty * 2 + 0) * SQ_STRIDE + lt * 64 + l);
            float4 p1 = *(const float4*)(Sq + (ty * 2 + 1) * SQ_STRIDE + lt * 64 + l);
            float p0f[4] = {p0.x, p0.y, p0.z, p0.w};
            float p1f[4] = {p1.x, p1.y, p1.z, p1.w};
#pragma unroll
            for (int kk = 0; kk < 4; kk++) {
                float4 v = *(const float4*)(KVs + (l + kk) * KV_STRIDE + tx * 4);
                cacc[0][0] += p0f[kk] * v.x; cacc[0][1] += p0f[kk] * v.y;
                cacc[0][2] += p0f[kk] * v.z; cacc[0][3] += p0f[kk] * v.w;
                cacc[1][0] += p1f[kk] * v.x; cacc[1][1] += p1f[kk] * v.y;
                cacc[1][2] += p1f[kk] * v.z; cacc[1][3] += p1f[kk] * v.w;
            }
        }
    }

#pragma unroll
    for (int i = 0; i < 2; i++) {
        size_t base = ((size_t)b * TQ + q0 + ty * 2 + i) * D_MODEL + h * 64 + tx * 4;
        float4 r = make_float4(cacc[i][0], cacc[i][1], cacc[i][2], cacc[i][3]);
        *(float4*)(g_ctx + base) = r;
    }
}

// ---------------------------------------------------------------------------
extern "C" void kernel_launch(void* const* d_in, const int* in_sizes, int n_in,
                              void* d_out, int out_size) {
    const float* q        = (const float*)d_in[0];
    const float* k        = (const float*)d_in[1];
    const float* v        = (const float*)d_in[2];
    const int*   src_mask = (const int*)d_in[3];
    const float* w_q      = (const float*)d_in[4];
    const float* b_q      = (const float*)d_in[5];
    const float* w_k      = (const float*)d_in[6];
    const float* b_k      = (const float*)d_in[7];
    const float* w_v      = (const float*)d_in[8];
    const float* b_v      = (const float*)d_in[9];
    const float* w_o      = (const float*)d_in[10];
    const float* b_o      = (const float*)d_in[11];
    float* out = (float*)d_out;

    cudaFuncSetAttribute(attn_kernel,
                         cudaFuncAttributeMaxDynamicSharedMemorySize,
                         ATTN_SMEM_BYTES);

    // Q proj: grid (N tiles, M tiles)
    tf32_gemm_kernel<128, 0><<<dim3(D_MODEL / 128, (B_SZ * TQ) / 128), 256>>>(
        q, w_q, b_q, nullptr);
    // K/V sliced proj: grid (L tiles, bh)
    tf32_gemm_kernel<64, 1><<<dim3(L_CTX / 128, B_SZ * N_HEAD), 256>>>(
        k, w_k, b_k, nullptr);
    tf32_gemm_kernel<64, 2><<<dim3(L_CTX / 128, B_SZ * N_HEAD), 256>>>(
        v, w_v, b_v, nullptr);

    attn_kernel<<<dim3(TQ / 32, B_SZ * N_HEAD), 256, ATTN_SMEM_BYTES>>>(src_mask);

    // O proj
    tf32_gemm_kernel<128, 3><<<dim3(D_MODEL / 128, (B_SZ * TQ) / 128), 256>>>(
        nullptr, w_o, b_o, out);
}

// round 3
// speedup vs baseline: 1.9400x; 1.4482x over previous
#include <cuda_runtime.h>
#include <cstdint>

#define D_MODEL 1024
#define N_HEAD 16
#define HEAD_DIM 64
#define B_SZ 4
#define TQ 2048
#define TK 8192
#define STRIDE 16
#define L_CTX 512

// Scratch (static device globals; no runtime allocation allowed)
__device__ float g_Qh[(size_t)B_SZ * N_HEAD * TQ * HEAD_DIM];      // [b][h][tq][d]
__device__ float g_Kh[(size_t)B_SZ * N_HEAD * L_CTX * HEAD_DIM];   // [b][h][l][d]
__device__ float g_Vh[(size_t)B_SZ * N_HEAD * L_CTX * HEAD_DIM];   // [b][h][l][d]
__device__ float g_ctx[(size_t)B_SZ * TQ * D_MODEL];               // [b][tq][h*64+d]

// ---------------------------------------------------------------------------
// tf32 helpers
// ---------------------------------------------------------------------------
__device__ __forceinline__ float tf32_round(float x) {
    uint32_t u;
    asm("cvt.rna.tf32.f32 %0, %1;" : "=r"(u) : "f"(x));
    return __uint_as_float(u);
}

__device__ __forceinline__ void mma_tf32(float* c, const uint32_t* a,
                                         uint32_t b0, uint32_t b1) {
    asm volatile(
        "mma.sync.aligned.m16n8k8.row.col.f32.tf32.tf32.f32 "
        "{%0,%1,%2,%3}, {%4,%5,%6,%7}, {%8,%9}, {%0,%1,%2,%3};\n"
        : "+f"(c[0]), "+f"(c[1]), "+f"(c[2]), "+f"(c[3])
        : "r"(a[0]), "r"(a[1]), "r"(a[2]), "r"(a[3]), "r"(b0), "r"(b1));
}

// ---------------------------------------------------------------------------
// tf32 GEMM with register-staged double buffering.
// MODE 0: Q proj, 1: K sliced, 2: V sliced, 3: O proj.
// Block 128xBN, BK=32, 256 threads (8 warps 4Mx2N), warp 32 x BN/2.
// ---------------------------------------------------------------------------
template <int BN, int MODE>
__global__ void __launch_bounds__(256, 2)
tf32_gemm_kernel(const float* __restrict__ Ain,
                 const float* __restrict__ W,
                 const float* __restrict__ bias,
                 float* __restrict__ Cout) {
    __shared__ float As[32][132];
    __shared__ float Ws[32][BN + 4];

    const int tid = threadIdx.x;
    const int lane = tid & 31, warp = tid >> 5;
    const int gid = lane >> 2, tig = lane & 3;

    int m0, bh = 0, h = 0, n_base = 0;
    const float* A;
    if (MODE == 1 || MODE == 2) {
        bh = blockIdx.y; int b = bh >> 4; h = bh & 15;
        m0 = blockIdx.x * 128;
        A = Ain + (size_t)b * TK * D_MODEL;
        n_base = h * 64;
    } else {
        m0 = blockIdx.y * 128;
        n_base = blockIdx.x * BN;
        A = (MODE == 3) ? g_ctx : Ain;
    }

    const int wm = (warp >> 1) * 32;
    const int wn = (warp & 1) * (BN / 2);
    constexpr int NF = BN / 16;
    constexpr int WL = BN / 32;

    float acc[2][NF][4] = {};
    float4 avS[4];
    float4 wvS[WL];

    auto LOAD = [&](int k0) {
#pragma unroll
        for (int i = 0; i < 4; i++) {
            int idx = tid + i * 256;
            int row = idx & 127, kc = (idx >> 7) * 4;
            int grow = (MODE == 1 || MODE == 2) ? (h + STRIDE * (m0 + row))
                                                : (m0 + row);
            avS[i] = *(const float4*)(A + (size_t)grow * D_MODEL + k0 + kc);
        }
#pragma unroll
        for (int i = 0; i < WL; i++) {
            int idx = tid + i * 256;
            int nrow = idx & (BN - 1), kc = (idx / BN) * 4;
            wvS[i] = *(const float4*)(W + (size_t)(n_base + nrow) * D_MODEL + k0 + kc);
        }
    };
    auto STORE = [&]() {
#pragma unroll
        for (int i = 0; i < 4; i++) {
            int idx = tid + i * 256;
            int row = idx & 127, kc = (idx >> 7) * 4;
            As[kc + 0][row] = tf32_round(avS[i].x);
            As[kc + 1][row] = tf32_round(avS[i].y);
            As[kc + 2][row] = tf32_round(avS[i].z);
            As[kc + 3][row] = tf32_round(avS[i].w);
        }
#pragma unroll
        for (int i = 0; i < WL; i++) {
            int idx = tid + i * 256;
            int nrow = idx & (BN - 1), kc = (idx / BN) * 4;
            Ws[kc + 0][nrow] = tf32_round(wvS[i].x);
            Ws[kc + 1][nrow] = tf32_round(wvS[i].y);
            Ws[kc + 2][nrow] = tf32_round(wvS[i].z);
            Ws[kc + 3][nrow] = tf32_round(wvS[i].w);
        }
    };
    auto MMA = [&]() {
#pragma unroll
        for (int ks = 0; ks < 32; ks += 8) {
            uint32_t a[2][4];
#pragma unroll
            for (int mi = 0; mi < 2; mi++) {
                int m = wm + mi * 16 + gid;
                a[mi][0] = __float_as_uint(As[ks + tig][m]);
                a[mi][1] = __float_as_uint(As[ks + tig][m + 8]);
                a[mi][2] = __float_as_uint(As[ks + tig + 4][m]);
                a[mi][3] = __float_as_uint(As[ks + tig + 4][m + 8]);
            }
#pragma unroll
            for (int ni = 0; ni < NF; ni++) {
                int n = wn + ni * 8 + gid;
                uint32_t b0 = __float_as_uint(Ws[ks + tig][n]);
                uint32_t b1 = __float_as_uint(Ws[ks + tig + 4][n]);
                mma_tf32(acc[0][ni], a[0], b0, b1);
                mma_tf32(acc[1][ni], a[1], b0, b1);
            }
        }
    };

    LOAD(0);
    STORE();
    __syncthreads();
#pragma unroll 1
    for (int k0 = 32; k0 < D_MODEL; k0 += 32) {
        LOAD(k0);
        MMA();
        __syncthreads();
        STORE();
        __syncthreads();
    }
    MMA();

    // --- writeback ---
#pragma unroll
    for (int mi = 0; mi < 2; mi++) {
#pragma unroll
        for (int ni = 0; ni < NF; ni++) {
#pragma unroll
            for (int r = 0; r < 4; r++) {
                int ml = wm + mi * 16 + gid + ((r >> 1) ? 8 : 0);
                int nl = wn + ni * 8 + 2 * tig + (r & 1);
                float v = acc[mi][ni][r];
                if (MODE == 0) {
                    int m = m0 + ml;
                    int n = n_base + nl;
                    int bb = m >> 11, tq = m & 2047;
                    int hh = n >> 6, d = n & 63;
                    g_Qh[(((size_t)bb * N_HEAD + hh) * TQ + tq) * HEAD_DIM + d] =
                        v + bias[n];
                } else if (MODE == 1) {
                    g_Kh[((size_t)bh * L_CTX + m0 + ml) * HEAD_DIM + nl] =
                        v + bias[n_base + nl];
                } else if (MODE == 2) {
                    g_Vh[((size_t)bh * L_CTX + m0 + ml) * HEAD_DIM + nl] =
                        v + bias[n_base + nl];
                } else {
                    Cout[(size_t)(m0 + ml) * D_MODEL + n_base + nl] =
                        v + bias[n_base + nl];
                }
            }
        }
    }
}

// ---------------------------------------------------------------------------
// Attention (mma): per block = 64 queries x one (b,h). 256 threads, 8 warps.
// Phase 1: S[64,512] = Q @ K^T (3xTF32 split for fp32-grade accuracy)
// Phase 2: softmax rows in smem
// Phase 3: O[64,64] = P @ V (single tf32)
// ---------------------------------------------------------------------------
#define AS_STRIDE 516
#define KT_STRIDE 68
#define ATTN_SMEM_BYTES ((64 * AS_STRIDE + 2 * 64 * KT_STRIDE) * 4 + L_CTX * 4)

__global__ void __launch_bounds__(256)
attn_kernel(const int* __restrict__ mask) {
    extern __shared__ float sm[];
    float* S   = sm;                          // [64][516]
    float* Khi = S + 64 * AS_STRIDE;          // [64][68]  (reused as V in ph3)
    float* Klo = Khi + 64 * KT_STRIDE;        // [64][68]
    int*   msk = (int*)(Klo + 64 * KT_STRIDE);   // [512]

    const int bh = blockIdx.y;
    const int b = bh >> 4, h = bh & 15;
    const int q0 = blockIdx.x * 64;
    const int tid = threadIdx.x;
    const int lane = tid & 31, warp = tid >> 5;
    const int gid = lane >> 2, tig = lane & 3;
    const int mw = warp & 3;      // M group (16 rows)
    const int nw = warp >> 2;     // N half (32 cols)
    const int lr = tid >> 2;            // tile-load row 0..63
    const int lc = (tid & 3) * 16;      // tile-load col base

    // gathered mask for this head
    for (int i = tid; i < L_CTX; i += 256)
        msk[i] = mask[(size_t)b * TK + h + STRIDE * i];

    // --- Q fragments (hi/lo split), loaded once from gmem ---
    const float* Qb = g_Qh + ((size_t)bh * TQ + q0) * HEAD_DIM;
    uint32_t qhi[8][4], qlo[8][4];
    {
        int r0 = mw * 16 + gid, r1 = r0 + 8;
#pragma unroll
        for (int ks = 0; ks < 8; ks++) {
            int c0 = ks * 8 + tig, c1 = c0 + 4;
            float x0 = Qb[r0 * 64 + c0], x1 = Qb[r1 * 64 + c0];
            float x2 = Qb[r0 * 64 + c1], x3 = Qb[r1 * 64 + c1];
            float h0 = tf32_round(x0), h1 = tf32_round(x1);
            float h2 = tf32_round(x2), h3 = tf32_round(x3);
            qhi[ks][0] = __float_as_uint(h0); qlo[ks][0] = __float_as_uint(tf32_round(x0 - h0));
            qhi[ks][1] = __float_as_uint(h1); qlo[ks][1] = __float_as_uint(tf32_round(x1 - h1));
            qhi[ks][2] = __float_as_uint(h2); qlo[ks][2] = __float_as_uint(tf32_round(x2 - h2));
            qhi[ks][3] = __float_as_uint(h3); qlo[ks][3] = __float_as_uint(tf32_round(x3 - h3));
        }
    }

    // ---------------- Phase 1: scores ----------------
    const float* Kb = g_Kh + (size_t)bh * L_CTX * HEAD_DIM;
    float4 pf[4];

    auto LOADK = [&](int kt) {
        const float4* src = (const float4*)(Kb + (size_t)(kt * 64 + lr) * 64 + lc);
        pf[0] = src[0]; pf[1] = src[1]; pf[2] = src[2]; pf[3] = src[3];
    };
    auto STOREK_SPLIT = [&]() {
#pragma unroll
        for (int j = 0; j < 4; j++) {
            float vals[4] = {pf[j].x, pf[j].y, pf[j].z, pf[j].w};
#pragma unroll
            for (int e = 0; e < 4; e++) {
                float x = vals[e];
                float hi = tf32_round(x);
                int off = lr * KT_STRIDE + lc + j * 4 + e;
                Khi[off] = hi;
                Klo[off] = tf32_round(x - hi);
            }
        }
    };

    LOADK(0);
    STOREK_SPLIT();
    __syncthreads();
#pragma unroll 1
    for (int kt = 0; kt < 8; kt++) {
        if (kt < 7) LOADK(kt + 1);

        float acc[4][4] = {};
#pragma unroll
        for (int ks = 0; ks < 8; ks++) {
#pragma unroll
            for (int ni = 0; ni < 4; ni++) {
                int n = nw * 32 + ni * 8 + gid;
                int c0 = ks * 8 + tig, c1 = c0 + 4;
                uint32_t bh0 = __float_as_uint(Khi[n * KT_STRIDE + c0]);
                uint32_t bh1 = __float_as_uint(Khi[n * KT_STRIDE + c1]);
                uint32_t bl0 = __float_as_uint(Klo[n * KT_STRIDE + c0]);
                uint32_t bl1 = __float_as_uint(Klo[n * KT_STRIDE + c1]);
                mma_tf32(acc[ni], qhi[ks], bh0, bh1);
                mma_tf32(acc[ni], qhi[ks], bl0, bl1);
                mma_tf32(acc[ni], qlo[ks], bh0, bh1);
            }
        }

        // scale + mask + store S
        int r0 = mw * 16 + gid;
#pragma unroll
        for (int ni = 0; ni < 4; ni++) {
            int col = kt * 64 + nw * 32 + ni * 8 + 2 * tig;
            float s00 = acc[ni][0] * 0.125f, s01 = acc[ni][1] * 0.125f;
            float s10 = acc[ni][2] * 0.125f, s11 = acc[ni][3] * 0.125f;
            if (msk[col] == 0)     { s00 = -1e9f; s10 = -1e9f; }
            if (msk[col + 1] == 0) { s01 = -1e9f; s11 = -1e9f; }
            *(float2*)&S[r0 * AS_STRIDE + col]       = make_float2(s00, s01);
            *(float2*)&S[(r0 + 8) * AS_STRIDE + col] = make_float2(s10, s11);
        }
        __syncthreads();
        if (kt < 7) {
            STOREK_SPLIT();
            __syncthreads();
        }
    }

    // ---------------- Phase 2: softmax (4 threads per row) ----------------
    {
        int row = tid >> 2, l4 = tid & 3;
        float* Sr = S + row * AS_STRIDE;
        float m = -1e30f;
        for (int l = l4; l < L_CTX; l += 4) m = fmaxf(m, Sr[l]);
        m = fmaxf(m, __shfl_xor_sync(0xffffffffu, m, 1));
        m = fmaxf(m, __shfl_xor_sync(0xffffffffu, m, 2));
        float ssum = 0.f;
        for (int l = l4; l < L_CTX; l += 4) {
            float e = __expf(Sr[l] - m);
            Sr[l] = e;
            ssum += e;
        }
        ssum += __shfl_xor_sync(0xffffffffu, ssum, 1);
        ssum += __shfl_xor_sync(0xffffffffu, ssum, 2);
        float inv = 1.0f / ssum;
        for (int l = l4; l < L_CTX; l += 4) Sr[l] = tf32_round(Sr[l] * inv);
    }
    __syncthreads();

    // ---------------- Phase 3: O = P @ V ----------------
    const float* Vb = g_Vh + (size_t)bh * L_CTX * HEAD_DIM;
    float* Vs = Khi;   // reuse
    float oacc[4][4] = {};

    auto LOADV = [&](int kt) {
        const float4* src = (const float4*)(Vb + (size_t)(kt * 64 + lr) * 64 + lc);
        pf[0] = src[0]; pf[1] = src[1]; pf[2] = src[2]; pf[3] = src[3];
    };
    auto STOREV = [&]() {
#pragma unroll
        for (int j = 0; j < 4; j++) {
            float vals[4] = {pf[j].x, pf[j].y, pf[j].z, pf[j].w};
#pragma unroll
            for (int e = 0; e < 4; e++)
                Vs[lr * KT_STRIDE + lc + j * 4 + e] = tf32_round(vals[e]);
        }
    };

    LOADV(0);
    STOREV();
    __syncthreads();
#pragma unroll 1
    for (int kt = 0; kt < 8; kt++) {
        if (kt < 7) LOADV(kt + 1);

        int r0 = mw * 16 + gid;
#pragma unroll
        for (int ks = 0; ks < 8; ks++) {
            int c0 = kt * 64 + ks * 8 + tig, c1 = c0 + 4;
            uint32_t a[4];
            a[0] = __float_as_uint(S[r0 * AS_STRIDE + c0]);
            a[1] = __float_as_uint(S[(r0 + 8) * AS_STRIDE + c0]);
            a[2] = __float_as_uint(S[r0 * AS_STRIDE + c1]);
            a[3] = __float_as_uint(S[(r0 + 8) * AS_STRIDE + c1]);
#pragma unroll
            for (int ni = 0; ni < 4; ni++) {
                int n = nw * 32 + ni * 8 + gid;
                uint32_t b0 = __float_as_uint(Vs[(ks * 8 + tig) * KT_STRIDE + n]);
                uint32_t b1 = __float_as_uint(Vs[(ks * 8 + tig + 4) * KT_STRIDE + n]);
                mma_tf32(oacc[ni], a, b0, b1);
            }
        }
        __syncthreads();
        if (kt < 7) {
            STOREV();
            __syncthreads();
        }
    }

    // writeback ctx[b][q][h*64+d]
    {
        int r0 = q0 + mw * 16 + gid;
#pragma unroll
        for (int ni = 0; ni < 4; ni++) {
            int col = h * 64 + nw * 32 + ni * 8 + 2 * tig;
            size_t base = ((size_t)b * TQ + r0) * D_MODEL + col;
            *(float2*)&g_ctx[base] = make_float2(oacc[ni][0], oacc[ni][1]);
            *(float2*)&g_ctx[base + (size_t)8 * D_MODEL] =
                make_float2(oacc[ni][2], oacc[ni][3]);
        }
    }
}

// ---------------------------------------------------------------------------
extern "C" void kernel_launch(void* const* d_in, const int* in_sizes, int n_in,
                              void* d_out, int out_size) {
    const float* q        = (const float*)d_in[0];
    const float* k        = (const float*)d_in[1];
    const float* v        = (const float*)d_in[2];
    const int*   src_mask = (const int*)d_in[3];
    const float* w_q      = (const float*)d_in[4];
    const float* b_q      = (const float*)d_in[5];
    const float* w_k      = (const float*)d_in[6];
    const float* b_k      = (const float*)d_in[7];
    const float* w_v      = (const float*)d_in[8];
    const float* b_v      = (const float*)d_in[9];
    const float* w_o      = (const float*)d_in[10];
    const float* b_o      = (const float*)d_in[11];
    float* out = (float*)d_out;

    cudaFuncSetAttribute(attn_kernel,
                         cudaFuncAttributeMaxDynamicSharedMemorySize,
                         ATTN_SMEM_BYTES);

    tf32_gemm_kernel<128, 0><<<dim3(D_MODEL / 128, (B_SZ * TQ) / 128), 256>>>(
        q, w_q, b_q, nullptr);
    tf32_gemm_kernel<64, 1><<<dim3(L_CTX / 128, B_SZ * N_HEAD), 256>>>(
        k, w_k, b_k, nullptr);
    tf32_gemm_kernel<64, 2><<<dim3(L_CTX / 128, B_SZ * N_HEAD), 256>>>(
        v, w_v, b_v, nullptr);

    attn_kernel<<<dim3(TQ / 64, B_SZ * N_HEAD), 256, ATTN_SMEM_BYTES>>>(src_mask);

    tf32_gemm_kernel<128, 3><<<dim3(D_MODEL / 128, (B_SZ * TQ) / 128), 256>>>(
        nullptr, w_o, b_o, out);
}

// round 4
// speedup vs baseline: 2.5923x; 1.3363x over previous
#include <cuda_runtime.h>
#include <cstdint>

#define D_MODEL 1024
#define N_HEAD 16
#define HEAD_DIM 64
#define B_SZ 4
#define TQ 2048
#define TK 8192
#define STRIDE 16
#define L_CTX 512

// Scratch (static device globals; no runtime allocation allowed)
__device__ float g_Qh[(size_t)B_SZ * N_HEAD * TQ * HEAD_DIM];      // [b][h][tq][d]
__device__ float g_Kh[(size_t)B_SZ * N_HEAD * L_CTX * HEAD_DIM];   // [b][h][l][d]
__device__ float g_Vh[(size_t)B_SZ * N_HEAD * L_CTX * HEAD_DIM];   // [b][h][l][d]
__device__ float g_ctx[(size_t)B_SZ * TQ * D_MODEL];               // [b][tq][h*64+d]

// ---------------------------------------------------------------------------
// tf32 helpers
// ---------------------------------------------------------------------------
__device__ __forceinline__ float tf32_round(float x) {
    uint32_t u;
    asm("cvt.rna.tf32.f32 %0, %1;" : "=r"(u) : "f"(x));
    return __uint_as_float(u);
}

__device__ __forceinline__ void mma_tf32(float* c, const uint32_t* a,
                                         uint32_t b0, uint32_t b1) {
    asm volatile(
        "mma.sync.aligned.m16n8k8.row.col.f32.tf32.tf32.f32 "
        "{%0,%1,%2,%3}, {%4,%5,%6,%7}, {%8,%9}, {%0,%1,%2,%3};\n"
        : "+f"(c[0]), "+f"(c[1]), "+f"(c[2]), "+f"(c[3])
        : "r"(a[0]), "r"(a[1]), "r"(a[2]), "r"(a[3]), "r"(b0), "r"(b1));
}

// ---------------------------------------------------------------------------
// tf32 GEMM with register-staged double buffering + coalesced tile loads.
// MODE 0: Q proj, 1: K sliced, 2: V sliced, 3: O proj.
// Block 128xBN, BK=32, 256 threads (8 warps 4Mx2N), warp 32 x BN/2.
// ---------------------------------------------------------------------------
template <int BN, int MODE>
__global__ void __launch_bounds__(256, 2)
tf32_gemm_kernel(const float* __restrict__ Ain,
                 const float* __restrict__ W,
                 const float* __restrict__ bias,
                 float* __restrict__ Cout) {
    __shared__ float As[32][132];
    __shared__ float Ws[32][BN + 4];

    const int tid = threadIdx.x;
    const int lane = tid & 31, warp = tid >> 5;
    const int gid = lane >> 2, tig = lane & 3;

    int m0, bh = 0, h = 0, n_base = 0;
    const float* A;
    if (MODE == 1 || MODE == 2) {
        bh = blockIdx.y; int b = bh >> 4; h = bh & 15;
        m0 = blockIdx.x * 128;
        A = Ain + (size_t)b * TK * D_MODEL;
        n_base = h * 64;
    } else {
        m0 = blockIdx.y * 128;
        n_base = blockIdx.x * BN;
        A = (MODE == 3) ? g_ctx : Ain;
    }

    const int wm = (warp >> 1) * 32;
    const int wn = (warp & 1) * (BN / 2);
    constexpr int NF = BN / 16;
    constexpr int WL = BN / 32;

    float acc[2][NF][4] = {};
    float4 avS[4];
    float4 wvS[WL];

    // coalesced: 8 consecutive threads cover one 128B row segment
    auto LOAD = [&](int k0) {
#pragma unroll
        for (int i = 0; i < 4; i++) {
            int idx = tid + i * 256;
            int row = idx >> 3, kc = (idx & 7) * 4;
            int grow = (MODE == 1 || MODE == 2) ? (h + STRIDE * (m0 + row))
                                                : (m0 + row);
            avS[i] = *(const float4*)(A + (size_t)grow * D_MODEL + k0 + kc);
        }
#pragma unroll
        for (int i = 0; i < WL; i++) {
            int idx = tid + i * 256;
            int nrow = idx >> 3, kc = (idx & 7) * 4;
            wvS[i] = *(const float4*)(W + (size_t)(n_base + nrow) * D_MODEL + k0 + kc);
        }
    };
    auto STORE = [&]() {
#pragma unroll
        for (int i = 0; i < 4; i++) {
            int idx = tid + i * 256;
            int row = idx >> 3, kc = (idx & 7) * 4;
            As[kc + 0][row] = tf32_round(avS[i].x);
            As[kc + 1][row] = tf32_round(avS[i].y);
            As[kc + 2][row] = tf32_round(avS[i].z);
            As[kc + 3][row] = tf32_round(avS[i].w);
        }
#pragma unroll
        for (int i = 0; i < WL; i++) {
            int idx = tid + i * 256;
            int nrow = idx >> 3, kc = (idx & 7) * 4;
            Ws[kc + 0][nrow] = tf32_round(wvS[i].x);
            Ws[kc + 1][nrow] = tf32_round(wvS[i].y);
            Ws[kc + 2][nrow] = tf32_round(wvS[i].z);
            Ws[kc + 3][nrow] = tf32_round(wvS[i].w);
        }
    };
    auto MMA = [&]() {
#pragma unroll
        for (int ks = 0; ks < 32; ks += 8) {
            uint32_t a[2][4];
#pragma unroll
            for (int mi = 0; mi < 2; mi++) {
                int m = wm + mi * 16 + gid;
                a[mi][0] = __float_as_uint(As[ks + tig][m]);
                a[mi][1] = __float_as_uint(As[ks + tig][m + 8]);
                a[mi][2] = __float_as_uint(As[ks + tig + 4][m]);
                a[mi][3] = __float_as_uint(As[ks + tig + 4][m + 8]);
            }
#pragma unroll
            for (int ni = 0; ni < NF; ni++) {
                int n = wn + ni * 8 + gid;
                uint32_t b0 = __float_as_uint(Ws[ks + tig][n]);
                uint32_t b1 = __float_as_uint(Ws[ks + tig + 4][n]);
                mma_tf32(acc[0][ni], a[0], b0, b1);
                mma_tf32(acc[1][ni], a[1], b0, b1);
            }
        }
    };

    LOAD(0);
    STORE();
    __syncthreads();
#pragma unroll 1
    for (int k0 = 32; k0 < D_MODEL; k0 += 32) {
        LOAD(k0);
        MMA();
        __syncthreads();
        STORE();
        __syncthreads();
    }
    MMA();

    // --- writeback ---
#pragma unroll
    for (int mi = 0; mi < 2; mi++) {
#pragma unroll
        for (int ni = 0; ni < NF; ni++) {
#pragma unroll
            for (int r = 0; r < 4; r++) {
                int ml = wm + mi * 16 + gid + ((r >> 1) ? 8 : 0);
                int nl = wn + ni * 8 + 2 * tig + (r & 1);
                float v = acc[mi][ni][r];
                if (MODE == 0) {
                    int m = m0 + ml;
                    int n = n_base + nl;
                    int bb = m >> 11, tq = m & 2047;
                    int hh = n >> 6, d = n & 63;
                    g_Qh[(((size_t)bb * N_HEAD + hh) * TQ + tq) * HEAD_DIM + d] =
                        v + bias[n];
                } else if (MODE == 1) {
                    g_Kh[((size_t)bh * L_CTX + m0 + ml) * HEAD_DIM + nl] =
                        v + bias[n_base + nl];
                } else if (MODE == 2) {
                    g_Vh[((size_t)bh * L_CTX + m0 + ml) * HEAD_DIM + nl] =
                        v + bias[n_base + nl];
                } else {
                    Cout[(size_t)(m0 + ml) * D_MODEL + n_base + nl] =
                        v + bias[n_base + nl];
                }
            }
        }
    }
}

// ---------------------------------------------------------------------------
// Flash attention: block = 64 queries x one (b,h). 128 threads, 4 warps.
// Warp w owns rows w*16..w*16+15 (full 64-col S stripe -> warp-local softmax).
// K streamed in 8 tiles of 64; online softmax; O accum in registers.
// All smem operands fragment-major (vector LDS, bank-spread via ks rotation).
// ---------------------------------------------------------------------------
#define AT_THREADS 128
#define OFF_QF   0
#define OFF_KHI  4096
#define OFF_KLO  (4096 + 5120)
#define OFF_VF   (4096 + 2 * 5120)
#define OFF_P    (4096 + 3 * 5120)
#define OFF_MSK  (OFF_P + 4 * 16 * 68)
#define AT_SMEM_BYTES ((OFF_MSK + 512) * 4)

__global__ void __launch_bounds__(128, 2)
attn_kernel(const int* __restrict__ mask) {
    extern __shared__ float sm[];
    float* Qf  = sm + OFF_QF;    // [ks8][mg4][lane32][slot4]
    float* Khi = sm + OFF_KHI;   // [ks8][n64][tig4(+pad1)][kh2]
    float* Klo = sm + OFF_KLO;
    float* Vf  = sm + OFF_VF;
    float* Pw  = sm + OFF_P;     // per-warp [16][68]
    int*   msk = (int*)(sm + OFF_MSK);

    const int bh = blockIdx.y;
    const int b = bh >> 4, h = bh & 15;
    const int q0 = blockIdx.x * 64;
    const int tid = threadIdx.x;
    const int lane = tid & 31, warp = tid >> 5;   // warp == m-group
    const int gid = lane >> 2, tig = lane & 3;

    for (int i = tid; i < L_CTX; i += AT_THREADS)
        msk[i] = mask[(size_t)b * TK + h + STRIDE * i];

    // Q tile -> fragment-major smem (fp32; split to hi/lo at use)
    const float* Qb = g_Qh + ((size_t)bh * TQ + q0) * HEAD_DIM;
#pragma unroll
    for (int i = 0; i < 8; i++) {
        int idx = tid + i * AT_THREADS;   // 0..1023
        int row = idx >> 4;               // 0..63
        int dc = (idx & 15) * 4;
        float4 v = *(const float4*)(Qb + row * 64 + dc);
        int mg = row >> 4, mh = (row >> 3) & 1, g = row & 7;
        float vv[4] = {v.x, v.y, v.z, v.w};
#pragma unroll
        for (int e = 0; e < 4; e++) {
            int d = dc + e;
            int ks = d >> 3, kh = (d >> 2) & 1, tg = d & 3;
            int ln = ((g * 4 + tg) + ks * 2) & 31;
            Qf[((ks * 4 + mg) * 32 + ln) * 4 + kh * 2 + mh] = vv[e];
        }
    }

    const float* Kb = g_Kh + (size_t)bh * L_CTX * HEAD_DIM;
    const float* Vb = g_Vh + (size_t)bh * L_CTX * HEAD_DIM;
    float* Pp = Pw + warp * (16 * 68);

    float oacc[8][4] = {};
    float M0 = -1e30f, M1 = -1e30f, L0 = 0.f, L1 = 0.f;

#pragma unroll 1
    for (int lt = 0; lt < 8; lt++) {
        __syncthreads();
        // cooperative K (hi/lo split) + V tile load, fragment-major
#pragma unroll
        for (int i = 0; i < 8; i++) {
            int idx = tid + i * AT_THREADS;
            int r = idx >> 4;               // row-in-tile 0..63
            int dc = (idx & 15) * 4;
            float4 kv = *(const float4*)(Kb + (size_t)(lt * 64 + r) * 64 + dc);
            float kk[4] = {kv.x, kv.y, kv.z, kv.w};
#pragma unroll
            for (int e = 0; e < 4; e++) {
                int d = dc + e;
                int ks = d >> 3, kh = (d >> 2) & 1, tg = d & 3;
                int ip = ((ks * 64 + r) * 5 + ((tg + ks) & 3)) * 2 + kh;
                float hi = tf32_round(kk[e]);
                Khi[ip] = hi;
                Klo[ip] = tf32_round(kk[e] - hi);
            }
            float4 vv = *(const float4*)(Vb + (size_t)(lt * 64 + r) * 64 + dc);
            float vl[4] = {vv.x, vv.y, vv.z, vv.w};
            int vks = r >> 3, vkh = (r >> 2) & 1;
            int vte = ((r & 3) + vks) & 3;
#pragma unroll
            for (int e = 0; e < 4; e++)
                Vf[((vks * 64 + (dc + e)) * 5 + vte) * 2 + vkh] = tf32_round(vl[e]);
        }
        __syncthreads();

        // ---- S = Q K^T (3x tf32 split) ----
        float sacc[8][4] = {};
#pragma unroll
        for (int ks = 0; ks < 8; ks++) {
            float4 qv = *(const float4*)&Qf[((ks * 4 + warp) * 32 +
                                             ((lane + ks * 2) & 31)) * 4];
            uint32_t ah[4], al[4];
            float q4[4] = {qv.x, qv.y, qv.z, qv.w};
#pragma unroll
            for (int j = 0; j < 4; j++) {
                float hi = tf32_round(q4[j]);
                ah[j] = __float_as_uint(hi);
                al[j] = __float_as_uint(tf32_round(q4[j] - hi));
            }
#pragma unroll
            for (int ni = 0; ni < 8; ni++) {
                int n = ni * 8 + gid;
                int ip = ((ks * 64 + n) * 5 + ((tig + ks) & 3)) * 2;
                float2 bh2 = *(const float2*)&Khi[ip];
                float2 bl2 = *(const float2*)&Klo[ip];
                uint32_t b0 = __float_as_uint(bh2.x), b1 = __float_as_uint(bh2.y);
                uint32_t c0 = __float_as_uint(bl2.x), c1 = __float_as_uint(bl2.y);
                mma_tf32(sacc[ni], ah, b0, b1);
                mma_tf32(sacc[ni], al, b0, b1);
                mma_tf32(sacc[ni], ah, c0, c1);
            }
        }

        // ---- scale + mask + online softmax (warp-local rows) ----
        float mt0 = -1e30f, mt1 = -1e30f;
#pragma unroll
        for (int ni = 0; ni < 8; ni++) {
            int c = lt * 64 + ni * 8 + 2 * tig;
            bool z0 = (msk[c] == 0), z1 = (msk[c + 1] == 0);
            sacc[ni][0] = z0 ? -1e9f : sacc[ni][0] * 0.125f;
            sacc[ni][1] = z1 ? -1e9f : sacc[ni][1] * 0.125f;
            sacc[ni][2] = z0 ? -1e9f : sacc[ni][2] * 0.125f;
            sacc[ni][3] = z1 ? -1e9f : sacc[ni][3] * 0.125f;
            mt0 = fmaxf(mt0, fmaxf(sacc[ni][0], sacc[ni][1]));
            mt1 = fmaxf(mt1, fmaxf(sacc[ni][2], sacc[ni][3]));
        }
        mt0 = fmaxf(mt0, __shfl_xor_sync(0xffffffffu, mt0, 1));
        mt0 = fmaxf(mt0, __shfl_xor_sync(0xffffffffu, mt0, 2));
        mt1 = fmaxf(mt1, __shfl_xor_sync(0xffffffffu, mt1, 1));
        mt1 = fmaxf(mt1, __shfl_xor_sync(0xffffffffu, mt1, 2));

        float Mn0 = fmaxf(M0, mt0), Mn1 = fmaxf(M1, mt1);
        float f0 = __expf(M0 - Mn0), f1 = __expf(M1 - Mn1);
        float s0 = 0.f, s1 = 0.f;
#pragma unroll
        for (int ni = 0; ni < 8; ni++) {
            int cc = ni * 8 + 2 * tig;
            float p00 = __expf(sacc[ni][0] - Mn0);
            float p01 = __expf(sacc[ni][1] - Mn0);
            float p10 = __expf(sacc[ni][2] - Mn1);
            float p11 = __expf(sacc[ni][3] - Mn1);
            s0 += p00 + p01; s1 += p10 + p11;
            Pp[gid * 68 + cc]           = tf32_round(p00);
            Pp[gid * 68 + cc + 1]       = tf32_round(p01);
            Pp[(gid + 8) * 68 + cc]     = tf32_round(p10);
            Pp[(gid + 8) * 68 + cc + 1] = tf32_round(p11);
        }
        s0 += __shfl_xor_sync(0xffffffffu, s0, 1);
        s0 += __shfl_xor_sync(0xffffffffu, s0, 2);
        s1 += __shfl_xor_sync(0xffffffffu, s1, 1);
        s1 += __shfl_xor_sync(0xffffffffu, s1, 2);
        L0 = L0 * f0 + s0; L1 = L1 * f1 + s1;
        M0 = Mn0; M1 = Mn1;
#pragma unroll
        for (int ni = 0; ni < 8; ni++) {
            oacc[ni][0] *= f0; oacc[ni][1] *= f0;
            oacc[ni][2] *= f1; oacc[ni][3] *= f1;
        }
        __syncwarp();

        // ---- O += P V ----
#pragma unroll
        for (int ks = 0; ks < 8; ks++) {
            uint32_t a[4];
            a[0] = __float_as_uint(Pp[gid * 68 + ks * 8 + tig]);
            a[1] = __float_as_uint(Pp[(gid + 8) * 68 + ks * 8 + tig]);
            a[2] = __float_as_uint(Pp[gid * 68 + ks * 8 + tig + 4]);
            a[3] = __float_as_uint(Pp[(gid + 8) * 68 + ks * 8 + tig + 4]);
#pragma unroll
            for (int ni = 0; ni < 8; ni++) {
                int n = ni * 8 + gid;
                int ip = ((ks * 64 + n) * 5 + ((tig + ks) & 3)) * 2;
                float2 bv = *(const float2*)&Vf[ip];
                mma_tf32(oacc[ni], a,
                         __float_as_uint(bv.x), __float_as_uint(bv.y));
            }
        }
    }

    // ---- epilogue: normalize + write ctx ----
    float inv0 = 1.0f / L0, inv1 = 1.0f / L1;
    int r0 = q0 + warp * 16 + gid;
#pragma unroll
    for (int ni = 0; ni < 8; ni++) {
        int col = h * 64 + ni * 8 + 2 * tig;
        size_t base0 = ((size_t)b * TQ + r0) * D_MODEL + col;
        *(float2*)&g_ctx[base0] =
            make_float2(oacc[ni][0] * inv0, oacc[ni][1] * inv0);
        *(float2*)&g_ctx[base0 + (size_t)8 * D_MODEL] =
            make_float2(oacc[ni][2] * inv1, oacc[ni][3] * inv1);
    }
}

// ---------------------------------------------------------------------------
extern "C" void kernel_launch(void* const* d_in, const int* in_sizes, int n_in,
                              void* d_out, int out_size) {
    const float* q        = (const float*)d_in[0];
    const float* k        = (const float*)d_in[1];
    const float* v        = (const float*)d_in[2];
    const int*   src_mask = (const int*)d_in[3];
    const float* w_q      = (const float*)d_in[4];
    const float* b_q      = (const float*)d_in[5];
    const float* w_k      = (const float*)d_in[6];
    const float* b_k      = (const float*)d_in[7];
    const float* w_v      = (const float*)d_in[8];
    const float* b_v      = (const float*)d_in[9];
    const float* w_o      = (const float*)d_in[10];
    const float* b_o      = (const float*)d_in[11];
    float* out = (float*)d_out;

    cudaFuncSetAttribute(attn_kernel,
                         cudaFuncAttributeMaxDynamicSharedMemorySize,
                         AT_SMEM_BYTES);

    tf32_gemm_kernel<128, 0><<<dim3(D_MODEL / 128, (B_SZ * TQ) / 128), 256>>>(
        q, w_q, b_q, nullptr);
    tf32_gemm_kernel<64, 1><<<dim3(L_CTX / 128, B_SZ * N_HEAD), 256>>>(
        k, w_k, b_k, nullptr);
    tf32_gemm_kernel<64, 2><<<dim3(L_CTX / 128, B_SZ * N_HEAD), 256>>>(
        v, w_v, b_v, nullptr);

    attn_kernel<<<dim3(TQ / 64, B_SZ * N_HEAD), 128, AT_SMEM_BYTES>>>(src_mask);

    tf32_gemm_kernel<128, 3><<<dim3(D_MODEL / 128, (B_SZ * TQ) / 128), 256>>>(
        nullptr, w_o, b_o, out);
}